// round 14
// baseline (speedup 1.0000x reference)
#include <cuda_runtime.h>

#define BATCH 32
#define SEQ   512
#define HID   512
#define G4    2048
#define NCTA  128
#define TPB   512
#define HSTR  132
#define PBS   148

typedef unsigned long long u64;

// ---------------- static device scratch ----------------
__device__ float g_zx0[(size_t)BATCH * SEQ * G4];
__device__ float g_h0[2][BATCH * HID];
__device__ float g_h1[2][BATCH * HID];
__device__ unsigned g_cnt0, g_cnt1;

// ---------------- packed f32x2 helpers ----------------
__device__ __forceinline__ u64 pk(float lo, float hi) {
    u64 r; asm("mov.b64 %0, {%1,%2};" : "=l"(r) : "f"(lo), "f"(hi)); return r;
}
__device__ __forceinline__ float2 upk(u64 v) {
    float2 r; asm("mov.b64 {%0,%1}, %2;" : "=f"(r.x), "=f"(r.y) : "l"(v)); return r;
}
__device__ __forceinline__ void fma2(u64 &acc, u64 a, u64 b) {
    asm("fma.rn.f32x2 %0, %1, %2, %0;" : "+l"(acc) : "l"(a), "l"(b));
}
__device__ __forceinline__ void arrive_release(unsigned* p) {
    asm volatile("red.release.gpu.global.add.u32 [%0], 1;" :: "l"(p) : "memory");
}
__device__ __forceinline__ unsigned ld_acquire_u(const unsigned* p) {
    unsigned v;
    asm volatile("ld.acquire.gpu.u32 %0, [%1];" : "=r"(v) : "l"(p) : "memory");
    return v;
}
__device__ __forceinline__ float sigf(float x)  { return 1.f / (1.f + __expf(-x)); }
__device__ __forceinline__ float tanhfa(float x){ return 2.f / (1.f + __expf(-2.f * x)) - 1.f; }

// cp.async helpers (L2-coherent 16B copies)
__device__ __forceinline__ void cp16(unsigned dst_smem, const void* src) {
    asm volatile("cp.async.cg.shared.global [%0], [%1], 16;" :: "r"(dst_smem), "l"(src) : "memory");
}
__device__ __forceinline__ void cp_commit() {
    asm volatile("cp.async.commit_group;" ::: "memory");
}
__device__ __forceinline__ void cp_wait0() {
    asm volatile("cp.async.wait_group 0;" ::: "memory");
}

// ---------------- init ----------------
__global__ void init_kernel() {
    int i = blockIdx.x * blockDim.x + threadIdx.x;
    if (i == 0) { g_cnt0 = 0u; g_cnt1 = 0u; }
    if (i < BATCH * HID) {
        g_h0[0][i] = 0.f; g_h0[1][i] = 0.f;
        g_h1[0][i] = 0.f; g_h1[1][i] = 0.f;
    }
}

// ---------------- embedding gather ----------------
__global__ void embed_kernel(const int* __restrict__ src,
                             const float* __restrict__ emb,
                             float* __restrict__ oe) {
    int bs = blockIdx.x;
    int tok = src[bs];
    const float4* er = (const float4*)(emb + (size_t)tok * HID);
    float4* orow = (float4*)(oe + (size_t)bs * HID);
    orow[threadIdx.x] = er[threadIdx.x];
}

// ---------------- precompute GEMM: Zx0 = X @ Wk0 + b0 ----------------
__global__ __launch_bounds__(256) void gemm_zx0(const float* __restrict__ X,
                                                const float* __restrict__ Wk,
                                                const float* __restrict__ bias) {
    __shared__ float As[16][128];
    __shared__ float Bs[16][128];
    const int bm = blockIdx.y * 128;
    const int bn = blockIdx.x * 128;
    const int tid = threadIdx.x;
    const int tx = tid & 15, ty = tid >> 4;

    u64 acc[4][8];
#pragma unroll
    for (int p = 0; p < 4; p++)
#pragma unroll
        for (int q = 0; q < 8; q++) acc[p][q] = 0ull;

    for (int k0 = 0; k0 < 512; k0 += 16) {
#pragma unroll
        for (int r = 0; r < 2; r++) {
            int i = tid + 256 * r;
            int m = i >> 2, kq = (i & 3) * 4;
            float4 v = *(const float4*)(X + (size_t)(bm + m) * 512 + k0 + kq);
            As[kq + 0][m] = v.x; As[kq + 1][m] = v.y;
            As[kq + 2][m] = v.z; As[kq + 3][m] = v.w;
        }
#pragma unroll
        for (int r = 0; r < 2; r++) {
            int i = tid + 256 * r;
            int k = i >> 5, n4 = (i & 31) * 4;
            *(float4*)&Bs[k][n4] = *(const float4*)(Wk + (size_t)(k0 + k) * G4 + bn + n4);
        }
        __syncthreads();
#pragma unroll
        for (int kk = 0; kk < 16; kk++) {
            u64 a0 = *(const u64*)&As[kk][ty * 8 + 0];
            u64 a1 = *(const u64*)&As[kk][ty * 8 + 2];
            u64 a2 = *(const u64*)&As[kk][ty * 8 + 4];
            u64 a3 = *(const u64*)&As[kk][ty * 8 + 6];
            float4 b0 = *(const float4*)&Bs[kk][tx * 8];
            float4 b1 = *(const float4*)&Bs[kk][tx * 8 + 4];
            u64 bb[8];
            bb[0] = pk(b0.x, b0.x); bb[1] = pk(b0.y, b0.y);
            bb[2] = pk(b0.z, b0.z); bb[3] = pk(b0.w, b0.w);
            bb[4] = pk(b1.x, b1.x); bb[5] = pk(b1.y, b1.y);
            bb[6] = pk(b1.z, b1.z); bb[7] = pk(b1.w, b1.w);
#pragma unroll
            for (int q = 0; q < 8; q++) {
                fma2(acc[0][q], a0, bb[q]);
                fma2(acc[1][q], a1, bb[q]);
                fma2(acc[2][q], a2, bb[q]);
                fma2(acc[3][q], a3, bb[q]);
            }
        }
        __syncthreads();
    }
#pragma unroll
    for (int p = 0; p < 4; p++) {
#pragma unroll
        for (int q = 0; q < 8; q++) {
            int m0 = bm + ty * 8 + 2 * p;
            int n = bn + tx * 8 + q;
            float bb = bias[n];
            float2 v = upk(acc[p][q]);
            g_zx0[(size_t)m0 * G4 + n]       = v.x + bb;
            g_zx0[(size_t)(m0 + 1) * G4 + n] = v.y + bb;
        }
    }
}

// ================= persistent recurrence =================
#define WS_FL    8192
#define HS_OFF   24576
#define PART_OFF 41472
#define SMEM_FL  46208

__device__ __forceinline__ void accumAB(u64* accA, u64* accB, const float* hs,
                                        const float* w0, const float* w1,
                                        int kseg, int c2, int bbase) {
    const int ch0 = kseg * 16;
    const float* wp0 = w0 + ch0 * 64 + c2 * 4;
    const float* wp1 = w1 + ch0 * 64 + c2 * 4;
    const float* hp  = hs + ch0 * HSTR;
#pragma unroll 8
    for (int t = 0; t < 16; t++) {
        ulonglong2 wa0 = *(const ulonglong2*)(wp0 + t * 64);
        ulonglong2 wb0 = *(const ulonglong2*)(wp0 + t * 64 + 32);
        ulonglong2 wa1 = *(const ulonglong2*)(wp1 + t * 64);
        ulonglong2 wb1 = *(const ulonglong2*)(wp1 + t * 64 + 32);
#pragma unroll
        for (int bi = 0; bi < 4; bi++) {
            const int b = bbase + bi * 4;
            ulonglong2 h = *(const ulonglong2*)(hp + t * HSTR + b * 4);
            fma2(accA[bi],     wa0.x, h.x); fma2(accA[bi],     wa0.y, h.y);
            fma2(accA[4 + bi], wb0.x, h.x); fma2(accA[4 + bi], wb0.y, h.y);
            fma2(accB[bi],     wa1.x, h.x); fma2(accB[bi],     wa1.y, h.y);
            fma2(accB[4 + bi], wb1.x, h.x); fma2(accB[4 + bi], wb1.y, h.y);
        }
    }
}

__device__ __forceinline__ void accum1(u64* acc, const float* hs, const float* wm,
                                       int kseg, int c2, int bbase) {
    const int ch0 = kseg * 16;
    const float* wp = wm + ch0 * 64 + c2 * 4;
    const float* hp = hs + ch0 * HSTR;
#pragma unroll 8
    for (int t = 0; t < 16; t++) {
        ulonglong2 wa = *(const ulonglong2*)(wp + t * 64);
        ulonglong2 wb = *(const ulonglong2*)(wp + t * 64 + 32);
#pragma unroll
        for (int bi = 0; bi < 4; bi++) {
            const int b = bbase + bi * 4;
            ulonglong2 h = *(const ulonglong2*)(hp + t * HSTR + b * 4);
            fma2(acc[bi],     wa.x, h.x); fma2(acc[bi],     wa.y, h.y);
            fma2(acc[4 + bi], wb.x, h.x); fma2(acc[4 + bi], wb.y, h.y);
        }
    }
}

__device__ __forceinline__ void dumpPf(float* part, const u64* acc,
                                       int kseg, int c2, int bbase) {
#pragma unroll
    for (int cc = 0; cc < 2; cc++)
#pragma unroll
        for (int bi = 0; bi < 4; bi++) {
            float2 v = upk(acc[cc * 4 + bi]);
            part[(bbase + bi * 4) * PBS + (c2 + 8 * cc) * 9 + kseg] = v.x + v.y;
        }
}

__device__ __forceinline__ float redcellf(const float* part, int rb, int rci) {
    const float* p = part + rb * PBS + rci * 9;
    return ((p[0] + p[1]) + (p[2] + p[3])) + ((p[4] + p[5]) + (p[6] + p[7]));
}

// synchronous stage (preloop only)
__device__ __forceinline__ void stage_h(float* hs, const float* __restrict__ src, int tid) {
    const int cidx = tid & 127;
    const int brow = tid >> 7;
#pragma unroll
    for (int i = 0; i < 8; i++) {
        const int b = brow * 8 + i;
        float4 v = __ldcg((const float4*)(src + b * HID + cidx * 4));
        *(float4*)(hs + cidx * HSTR + b * 4) = v;
    }
}

// async stage: issue cp.async.cg copies; caller does cp_wait0() before barrier
__device__ __forceinline__ void stage_h_async(unsigned hs_sm, const float* __restrict__ src, int tid) {
    const int cidx = tid & 127;
    const int brow = tid >> 7;
#pragma unroll
    for (int i = 0; i < 8; i++) {
        const int b = brow * 8 + i;
        cp16(hs_sm + (unsigned)((cidx * HSTR + b * 4) * 4), src + b * HID + cidx * 4);
    }
    cp_commit();
}

__global__ __launch_bounds__(TPB, 1) void persist_kernel(const float* __restrict__ Wk,
                                                         const float* __restrict__ Wr,
                                                         const float* __restrict__ bias,
                                                         float* __restrict__ out) {
    extern __shared__ float smf[];
    float* ws0 = smf;
    float* ws1 = smf + WS_FL;
    float* ws2 = smf + 2 * WS_FL;
    float* hs  = smf + HS_OFF;
    float* part = smf + PART_OFF;
    const unsigned hs_sm = (unsigned)__cvta_generic_to_shared(hs);

    const int tid = threadIdx.x;
    const int cid = blockIdx.x;
    const int u0 = cid * 4;
    const int lane = tid & 31;
    const int kseg = (tid >> 5) >> 1;
    const int bhalf = (tid >> 5) & 1;
    const int c2 = lane & 7;
    const int bg = lane >> 3;
    const int bbase = bhalf * 16 + bg;

    // ---- stage weights once ----
    {
        const float* wsrcs[3] = { Wr, Wk + (size_t)HID * G4, Wr + (size_t)HID * G4 };
        float* wdsts[3] = { ws0, ws1, ws2 };
#pragma unroll
        for (int m = 0; m < 3; m++) {
            const float* srcm = wsrcs[m];
            float* dst = wdsts[m];
            for (int i = 0; i < 4; i++) {
                int t2 = tid + TPB * i;
                int g = t2 & 3, k = t2 >> 2;
                float4 v = __ldcg((const float4*)(srcm + (size_t)k * G4 + g * HID + u0));
                int ch = k >> 2, kk = k & 3;
                float* d = dst + ch * 64 + g * 16 + kk;
                d[0]  = v.x; d[4]  = v.y; d[8]  = v.z; d[12] = v.w;
            }
        }
    }

    const int rb = tid >> 4, rci = tid & 15;
    const int rcol = (rci >> 2) * HID + u0 + (rci & 3);
    const float biasB = bias[G4 + rcol];

    const int ul = lane & 3;
    const bool isGate = (lane & 15) < 4;
    const int shbase = lane & 16;
    float c0reg = 0.f, c1reg = 0.f;

    const bool isPoll = (lane == 4);

    // pre-loop: stage h0 initial state (zeros)
    stage_h(hs, g_h0[0], tid);
    __syncthreads();

    for (int j = 0; j <= SEQ; j++) {
        const int rbuf = j & 1, wb2 = rbuf ^ 1;
        const unsigned tgt = (unsigned)(NCTA * (j + 1));

        // ---- P2: arrive cnt1; zx prefetch; fused A+B from hs(=h0); dumpA; poll cnt1 ----
        if (tid == 0) arrive_release(&g_cnt1);
        float zx = 0.f;
        if (j < SEQ)
            zx = __ldcg(&g_zx0[((size_t)(rb * SEQ + j)) * G4 + rcol]);
        u64 accA[8], accB[8];
#pragma unroll
        for (int q = 0; q < 8; q++) { accA[q] = 0ull; accB[q] = 0ull; }
        accumAB(accA, accB, hs, ws0, ws1, kseg, c2, bbase);
        dumpPf(part, accA, kseg, c2, bbase);
        if (isPoll) {
            while (ld_acquire_u(&g_cnt1) < tgt) { }
        }
        __syncthreads();

        // ---- P3: async stage hs <- h1(t=j-2) FIRST, then reduce zA + gates0 + store h0(t=j) ----
        stage_h_async(hs_sm, g_h1[rbuf], tid);
        {
            float z = redcellf(part, rb, rci) + zx;
            float zi = __shfl_sync(0xffffffffu, z, shbase | ul);
            float zf = __shfl_sync(0xffffffffu, z, shbase | (ul + 4));
            float zg = __shfl_sync(0xffffffffu, z, shbase | (ul + 8));
            float zo = __shfl_sync(0xffffffffu, z, shbase | (ul + 12));
            if (isGate && j < SEQ) {
                float ig = sigf(zi), fg = sigf(zf), gg = tanhfa(zg), og = sigf(zo);
                c0reg = fg * c0reg + ig * gg;
                float hn = og * tanhfa(c0reg);
                g_h0[wb2][rb * HID + u0 + ul] = hn;
            }
        }
        cp_wait0();
        __syncthreads();

        // ---- P4: arrive cnt0; C = Wr1.h1 into accB; dumpB; poll cnt0 ----
        if (tid == 0) arrive_release(&g_cnt0);
        accum1(accB, hs, ws2, kseg, c2, bbase);
        dumpPf(part, accB, kseg, c2, bbase);
        if (isPoll && j < SEQ) {
            while (ld_acquire_u(&g_cnt0) < tgt) { }
        }
        __syncthreads();

        // ---- P5: async stage hs <- h0(t=j) FIRST (certified by cnt0 poll),
        //          then reduce zB + gates1 + store h1(t=j-1) + out ----
        if (j < SEQ)
            stage_h_async(hs_sm, g_h0[wb2], tid);
        {
            float z = redcellf(part, rb, rci) + biasB;
            float zi = __shfl_sync(0xffffffffu, z, shbase | ul);
            float zf = __shfl_sync(0xffffffffu, z, shbase | (ul + 4));
            float zg = __shfl_sync(0xffffffffu, z, shbase | (ul + 8));
            float zo = __shfl_sync(0xffffffffu, z, shbase | (ul + 12));
            if (isGate && j >= 1) {
                float ig = sigf(zi), fg = sigf(zf), gg = tanhfa(zg), og = sigf(zo);
                c1reg = fg * c1reg + ig * gg;
                float hn = og * tanhfa(c1reg);
                g_h1[wb2][rb * HID + u0 + ul] = hn;
                out[(size_t)rb * SEQ * HID + (size_t)(j - 1) * HID + u0 + ul] = hn;
            }
        }
        if (j < SEQ) cp_wait0();
        __syncthreads();                   // step end: fences h1/out stores for next arrive
    }
}

// ---------------- launch ----------------
extern "C" void kernel_launch(void* const* d_in, const int* in_sizes, int n_in,
                              void* d_out, int out_size) {
    const int*   src  = (const int*)  d_in[0];
    const float* emb  = (const float*)d_in[2];
    const float* Wk   = (const float*)d_in[3];
    const float* Wr   = (const float*)d_in[4];
    const float* bias = (const float*)d_in[5];
    float* out = (float*)d_out;
    float* out_emb = out + (size_t)BATCH * SEQ * HID;

    init_kernel<<<64, 256>>>();
    embed_kernel<<<BATCH * SEQ, 128>>>(src, emb, out_emb);
    gemm_zx0<<<dim3(G4 / 128, (BATCH * SEQ) / 128), 256>>>(out_emb, Wk, bias);

    cudaFuncSetAttribute(persist_kernel, cudaFuncAttributeMaxDynamicSharedMemorySize, SMEM_FL * 4);
    persist_kernel<<<NCTA, TPB, SMEM_FL * 4>>>(Wk, Wr, bias, out);
}

// round 15
// speedup vs baseline: 1.2575x; 1.2575x over previous
#include <cuda_runtime.h>

#define BATCH 32
#define SEQ   512
#define HID   512
#define G4    2048
#define NCTA  128
#define TPB   512
#define HSTR  132
#define PBS   148

typedef unsigned long long u64;

// ---------------- static device scratch ----------------
__device__ float g_zx0[(size_t)BATCH * SEQ * G4];
__device__ float g_h0[2][BATCH * HID];
__device__ float g_h1[2][BATCH * HID];
__device__ unsigned g_cnt0, g_cnt1;

// ---------------- packed f32x2 helpers ----------------
__device__ __forceinline__ u64 pk(float lo, float hi) {
    u64 r; asm("mov.b64 %0, {%1,%2};" : "=l"(r) : "f"(lo), "f"(hi)); return r;
}
__device__ __forceinline__ float2 upk(u64 v) {
    float2 r; asm("mov.b64 {%0,%1}, %2;" : "=f"(r.x), "=f"(r.y) : "l"(v)); return r;
}
__device__ __forceinline__ void fma2(u64 &acc, u64 a, u64 b) {
    asm("fma.rn.f32x2 %0, %1, %2, %0;" : "+l"(acc) : "l"(a), "l"(b));
}
__device__ __forceinline__ void arrive_release(unsigned* p) {
    asm volatile("red.release.gpu.global.add.u32 [%0], 1;" :: "l"(p) : "memory");
}
__device__ __forceinline__ unsigned ld_acquire_u(const unsigned* p) {
    unsigned v;
    asm volatile("ld.acquire.gpu.u32 %0, [%1];" : "=r"(v) : "l"(p) : "memory");
    return v;
}
__device__ __forceinline__ float sigf(float x)  { return 1.f / (1.f + __expf(-x)); }
__device__ __forceinline__ float tanhfa(float x){ return 2.f / (1.f + __expf(-2.f * x)) - 1.f; }

// ---------------- init ----------------
__global__ void init_kernel() {
    int i = blockIdx.x * blockDim.x + threadIdx.x;
    if (i == 0) { g_cnt0 = 0u; g_cnt1 = 0u; }
    if (i < BATCH * HID) {
        g_h0[0][i] = 0.f; g_h0[1][i] = 0.f;
        g_h1[0][i] = 0.f; g_h1[1][i] = 0.f;
    }
}

// ---------------- embedding gather ----------------
__global__ void embed_kernel(const int* __restrict__ src,
                             const float* __restrict__ emb,
                             float* __restrict__ oe) {
    int bs = blockIdx.x;
    int tok = src[bs];
    const float4* er = (const float4*)(emb + (size_t)tok * HID);
    float4* orow = (float4*)(oe + (size_t)bs * HID);
    orow[threadIdx.x] = er[threadIdx.x];
}

// ---------------- precompute GEMM: Zx0 = X @ Wk0 + b0 ----------------
__global__ __launch_bounds__(256) void gemm_zx0(const float* __restrict__ X,
                                                const float* __restrict__ Wk,
                                                const float* __restrict__ bias) {
    __shared__ float As[16][128];
    __shared__ float Bs[16][128];
    const int bm = blockIdx.y * 128;
    const int bn = blockIdx.x * 128;
    const int tid = threadIdx.x;
    const int tx = tid & 15, ty = tid >> 4;

    u64 acc[4][8];
#pragma unroll
    for (int p = 0; p < 4; p++)
#pragma unroll
        for (int q = 0; q < 8; q++) acc[p][q] = 0ull;

    for (int k0 = 0; k0 < 512; k0 += 16) {
#pragma unroll
        for (int r = 0; r < 2; r++) {
            int i = tid + 256 * r;
            int m = i >> 2, kq = (i & 3) * 4;
            float4 v = *(const float4*)(X + (size_t)(bm + m) * 512 + k0 + kq);
            As[kq + 0][m] = v.x; As[kq + 1][m] = v.y;
            As[kq + 2][m] = v.z; As[kq + 3][m] = v.w;
        }
#pragma unroll
        for (int r = 0; r < 2; r++) {
            int i = tid + 256 * r;
            int k = i >> 5, n4 = (i & 31) * 4;
            *(float4*)&Bs[k][n4] = *(const float4*)(Wk + (size_t)(k0 + k) * G4 + bn + n4);
        }
        __syncthreads();
#pragma unroll
        for (int kk = 0; kk < 16; kk++) {
            u64 a0 = *(const u64*)&As[kk][ty * 8 + 0];
            u64 a1 = *(const u64*)&As[kk][ty * 8 + 2];
            u64 a2 = *(const u64*)&As[kk][ty * 8 + 4];
            u64 a3 = *(const u64*)&As[kk][ty * 8 + 6];
            float4 b0 = *(const float4*)&Bs[kk][tx * 8];
            float4 b1 = *(const float4*)&Bs[kk][tx * 8 + 4];
            u64 bb[8];
            bb[0] = pk(b0.x, b0.x); bb[1] = pk(b0.y, b0.y);
            bb[2] = pk(b0.z, b0.z); bb[3] = pk(b0.w, b0.w);
            bb[4] = pk(b1.x, b1.x); bb[5] = pk(b1.y, b1.y);
            bb[6] = pk(b1.z, b1.z); bb[7] = pk(b1.w, b1.w);
#pragma unroll
            for (int q = 0; q < 8; q++) {
                fma2(acc[0][q], a0, bb[q]);
                fma2(acc[1][q], a1, bb[q]);
                fma2(acc[2][q], a2, bb[q]);
                fma2(acc[3][q], a3, bb[q]);
            }
        }
        __syncthreads();
    }
#pragma unroll
    for (int p = 0; p < 4; p++) {
#pragma unroll
        for (int q = 0; q < 8; q++) {
            int m0 = bm + ty * 8 + 2 * p;
            int n = bn + tx * 8 + q;
            float bb = bias[n];
            float2 v = upk(acc[p][q]);
            g_zx0[(size_t)m0 * G4 + n]       = v.x + bb;
            g_zx0[(size_t)(m0 + 1) * G4 + n] = v.y + bb;
        }
    }
}

// ================= persistent recurrence =================
#define WS_FL    8192
#define HS_OFF   24576
#define PART_OFF 41472
#define SMEM_FL  46208

__device__ __forceinline__ void accumAB(u64* accA, u64* accB, const float* hs,
                                        const float* w0, const float* w1,
                                        int kseg, int c2, int bbase) {
    const int ch0 = kseg * 16;
    const float* wp0 = w0 + ch0 * 64 + c2 * 4;
    const float* wp1 = w1 + ch0 * 64 + c2 * 4;
    const float* hp  = hs + ch0 * HSTR;
#pragma unroll 8
    for (int t = 0; t < 16; t++) {
        ulonglong2 wa0 = *(const ulonglong2*)(wp0 + t * 64);
        ulonglong2 wb0 = *(const ulonglong2*)(wp0 + t * 64 + 32);
        ulonglong2 wa1 = *(const ulonglong2*)(wp1 + t * 64);
        ulonglong2 wb1 = *(const ulonglong2*)(wp1 + t * 64 + 32);
#pragma unroll
        for (int bi = 0; bi < 4; bi++) {
            const int b = bbase + bi * 4;
            ulonglong2 h = *(const ulonglong2*)(hp + t * HSTR + b * 4);
            fma2(accA[bi],     wa0.x, h.x); fma2(accA[bi],     wa0.y, h.y);
            fma2(accA[4 + bi], wb0.x, h.x); fma2(accA[4 + bi], wb0.y, h.y);
            fma2(accB[bi],     wa1.x, h.x); fma2(accB[bi],     wa1.y, h.y);
            fma2(accB[4 + bi], wb1.x, h.x); fma2(accB[4 + bi], wb1.y, h.y);
        }
    }
}

__device__ __forceinline__ void accum1(u64* acc, const float* hs, const float* wm,
                                       int kseg, int c2, int bbase) {
    const int ch0 = kseg * 16;
    const float* wp = wm + ch0 * 64 + c2 * 4;
    const float* hp = hs + ch0 * HSTR;
#pragma unroll 8
    for (int t = 0; t < 16; t++) {
        ulonglong2 wa = *(const ulonglong2*)(wp + t * 64);
        ulonglong2 wb = *(const ulonglong2*)(wp + t * 64 + 32);
#pragma unroll
        for (int bi = 0; bi < 4; bi++) {
            const int b = bbase + bi * 4;
            ulonglong2 h = *(const ulonglong2*)(hp + t * HSTR + b * 4);
            fma2(acc[bi],     wa.x, h.x); fma2(acc[bi],     wa.y, h.y);
            fma2(acc[4 + bi], wb.x, h.x); fma2(acc[4 + bi], wb.y, h.y);
        }
    }
}

__device__ __forceinline__ void dumpPf(float* part, const u64* acc,
                                       int kseg, int c2, int bbase) {
#pragma unroll
    for (int cc = 0; cc < 2; cc++)
#pragma unroll
        for (int bi = 0; bi < 4; bi++) {
            float2 v = upk(acc[cc * 4 + bi]);
            part[(bbase + bi * 4) * PBS + (c2 + 8 * cc) * 9 + kseg] = v.x + v.y;
        }
}

__device__ __forceinline__ float redcellf(const float* part, int rb, int rci) {
    const float* p = part + rb * PBS + rci * 9;
    return ((p[0] + p[1]) + (p[2] + p[3])) + ((p[4] + p[5]) + (p[6] + p[7]));
}

// synchronous stage (preloop)
__device__ __forceinline__ void stage_h(float* hs, const float* __restrict__ src, int tid) {
    const int cidx = tid & 127;
    const int brow = tid >> 7;
#pragma unroll
    for (int i = 0; i < 8; i++) {
        const int b = brow * 8 + i;
        float4 v = __ldcg((const float4*)(src + b * HID + cidx * 4));
        *(float4*)(hs + cidx * HSTR + b * 4) = v;
    }
}

__global__ __launch_bounds__(TPB, 1) void persist_kernel(const float* __restrict__ Wk,
                                                         const float* __restrict__ Wr,
                                                         const float* __restrict__ bias,
                                                         float* __restrict__ out) {
    extern __shared__ float smf[];
    float* ws0 = smf;
    float* ws1 = smf + WS_FL;
    float* ws2 = smf + 2 * WS_FL;
    float* hs  = smf + HS_OFF;
    float* part = smf + PART_OFF;

    const int tid = threadIdx.x;
    const int cid = blockIdx.x;
    const int u0 = cid * 4;
    const int lane = tid & 31;
    const int kseg = (tid >> 5) >> 1;
    const int bhalf = (tid >> 5) & 1;
    const int c2 = lane & 7;
    const int bg = lane >> 3;
    const int bbase = bhalf * 16 + bg;
    const int cidx = tid & 127;       // staging chunk
    const int brow = tid >> 7;        // staging batch base

    // ---- stage weights once ----
    {
        const float* wsrcs[3] = { Wr, Wk + (size_t)HID * G4, Wr + (size_t)HID * G4 };
        float* wdsts[3] = { ws0, ws1, ws2 };
#pragma unroll
        for (int m = 0; m < 3; m++) {
            const float* srcm = wsrcs[m];
            float* dst = wdsts[m];
            for (int i = 0; i < 4; i++) {
                int t2 = tid + TPB * i;
                int g = t2 & 3, k = t2 >> 2;
                float4 v = __ldcg((const float4*)(srcm + (size_t)k * G4 + g * HID + u0));
                int ch = k >> 2, kk = k & 3;
                float* d = dst + ch * 64 + g * 16 + kk;
                d[0]  = v.x; d[4]  = v.y; d[8]  = v.z; d[12] = v.w;
            }
        }
    }

    const int rb = tid >> 4, rci = tid & 15;
    const int rcol = (rci >> 2) * HID + u0 + (rci & 3);
    const float biasB = bias[G4 + rcol];

    const int ul = lane & 3;
    const bool isGate = (lane & 15) < 4;
    const int shbase = lane & 16;
    float c0reg = 0.f, c1reg = 0.f;

    const bool isPoll = (lane == 4);

    // pre-loop: stage h0 initial state (zeros)
    stage_h(hs, g_h0[0], tid);
    __syncthreads();

    for (int j = 0; j <= SEQ; j++) {
        const int rbuf = j & 1, wb2 = rbuf ^ 1;
        const unsigned tgt = (unsigned)(NCTA * (j + 1));

        // ---- P2: arrive cnt1; zx prefetch; fused A+B from hs(=h0); dumpA; poll cnt1 ----
        if (tid == 0) arrive_release(&g_cnt1);
        float zx = 0.f;
        if (j < SEQ)
            zx = __ldcg(&g_zx0[((size_t)(rb * SEQ + j)) * G4 + rcol]);
        u64 accA[8], accB[8];
#pragma unroll
        for (int q = 0; q < 8; q++) { accA[q] = 0ull; accB[q] = 0ull; }
        if (j < SEQ) {
            accumAB(accA, accB, hs, ws0, ws1, kseg, c2, bbase);
            dumpPf(part, accA, kseg, c2, bbase);
        } else {
            accum1(accB, hs, ws1, kseg, c2, bbase);   // j=SEQ: only B needed
        }
        if (isPoll) {
            while (ld_acquire_u(&g_cnt1) < tgt) { }
        }
        __syncthreads();

        // ---- P3: prefetch first half of h1(t=j-2) into regs; reduce zA + gates0
        //          + store h0(t=j); flush; stage trailing half ----
        {
            const float* h1src = g_h1[rbuf];
            float4 hv0, hv1, hv2, hv3;
            hv0 = __ldcg((const float4*)(h1src + (brow * 8 + 0) * HID + cidx * 4));
            hv1 = __ldcg((const float4*)(h1src + (brow * 8 + 1) * HID + cidx * 4));
            hv2 = __ldcg((const float4*)(h1src + (brow * 8 + 2) * HID + cidx * 4));
            hv3 = __ldcg((const float4*)(h1src + (brow * 8 + 3) * HID + cidx * 4));
            if (j < SEQ) {
                float z = redcellf(part, rb, rci) + zx;
                float zi = __shfl_sync(0xffffffffu, z, shbase | ul);
                float zf = __shfl_sync(0xffffffffu, z, shbase | (ul + 4));
                float zg = __shfl_sync(0xffffffffu, z, shbase | (ul + 8));
                float zo = __shfl_sync(0xffffffffu, z, shbase | (ul + 12));
                if (isGate) {
                    float ig = sigf(zi), fg = sigf(zf), gg = tanhfa(zg), og = sigf(zo);
                    c0reg = fg * c0reg + ig * gg;
                    float hn = og * tanhfa(c0reg);
                    g_h0[wb2][rb * HID + u0 + ul] = hn;
                }
            }
            float* hdst = hs + cidx * HSTR;
            *(float4*)(hdst + (brow * 8 + 0) * 4) = hv0;
            *(float4*)(hdst + (brow * 8 + 1) * 4) = hv1;
            *(float4*)(hdst + (brow * 8 + 2) * 4) = hv2;
            *(float4*)(hdst + (brow * 8 + 3) * 4) = hv3;
            hv0 = __ldcg((const float4*)(h1src + (brow * 8 + 4) * HID + cidx * 4));
            hv1 = __ldcg((const float4*)(h1src + (brow * 8 + 5) * HID + cidx * 4));
            hv2 = __ldcg((const float4*)(h1src + (brow * 8 + 6) * HID + cidx * 4));
            hv3 = __ldcg((const float4*)(h1src + (brow * 8 + 7) * HID + cidx * 4));
            *(float4*)(hdst + (brow * 8 + 4) * 4) = hv0;
            *(float4*)(hdst + (brow * 8 + 5) * 4) = hv1;
            *(float4*)(hdst + (brow * 8 + 6) * 4) = hv2;
            *(float4*)(hdst + (brow * 8 + 7) * 4) = hv3;
        }
        __syncthreads();

        // ---- P4: arrive cnt0; C = Wr1.h1 into accB; dumpB; poll cnt0 ----
        if (tid == 0) arrive_release(&g_cnt0);
        accum1(accB, hs, ws2, kseg, c2, bbase);
        dumpPf(part, accB, kseg, c2, bbase);
        if (isPoll && j < SEQ) {
            while (ld_acquire_u(&g_cnt0) < tgt) { }
        }
        __syncthreads();

        // ---- P5: prefetch ALL of h0(t=j) into regs (acc dead; certified by cnt0 poll);
        //          reduce zB + gates1 + out; flush ----
        {
            float4 hv[8];
            const float* h0src = g_h0[wb2];
            if (j < SEQ) {
#pragma unroll
                for (int i = 0; i < 8; i++)
                    hv[i] = __ldcg((const float4*)(h0src + (brow * 8 + i) * HID + cidx * 4));
            }
            float z = redcellf(part, rb, rci) + biasB;
            float zi = __shfl_sync(0xffffffffu, z, shbase | ul);
            float zf = __shfl_sync(0xffffffffu, z, shbase | (ul + 4));
            float zg = __shfl_sync(0xffffffffu, z, shbase | (ul + 8));
            float zo = __shfl_sync(0xffffffffu, z, shbase | (ul + 12));
            if (isGate && j >= 1) {
                float ig = sigf(zi), fg = sigf(zf), gg = tanhfa(zg), og = sigf(zo);
                c1reg = fg * c1reg + ig * gg;
                float hn = og * tanhfa(c1reg);
                g_h1[wb2][rb * HID + u0 + ul] = hn;
                out[(size_t)rb * SEQ * HID + (size_t)(j - 1) * HID + u0 + ul] = hn;
            }
            if (j < SEQ) {
                float* hdst = hs + cidx * HSTR;
#pragma unroll
                for (int i = 0; i < 8; i++)
                    *(float4*)(hdst + (brow * 8 + i) * 4) = hv[i];
            }
        }
        __syncthreads();                   // step end: fences h1/out stores for next arrive
    }
}

// ---------------- launch ----------------
extern "C" void kernel_launch(void* const* d_in, const int* in_sizes, int n_in,
                              void* d_out, int out_size) {
    const int*   src  = (const int*)  d_in[0];
    const float* emb  = (const float*)d_in[2];
    const float* Wk   = (const float*)d_in[3];
    const float* Wr   = (const float*)d_in[4];
    const float* bias = (const float*)d_in[5];
    float* out = (float*)d_out;
    float* out_emb = out + (size_t)BATCH * SEQ * HID;

    init_kernel<<<64, 256>>>();
    embed_kernel<<<BATCH * SEQ, 128>>>(src, emb, out_emb);
    gemm_zx0<<<dim3(G4 / 128, (BATCH * SEQ) / 128), 256>>>(out_emb, Wk, bias);

    cudaFuncSetAttribute(persist_kernel, cudaFuncAttributeMaxDynamicSharedMemorySize, SMEM_FL * 4);
    persist_kernel<<<NCTA, TPB, SMEM_FL * 4>>>(Wk, Wr, bias, out);
}